// round 1
// baseline (speedup 1.0000x reference)
#include <cuda_runtime.h>
#include <cuda_bf16.h>
#include <cstdint>

#define GR 8
#define BATCH 32
#define TT 512
#define HGD 128
#define ROWS 384          // 3 * HGD
#define PADW 388          // smem row stride (floats) for W[k][o]
#define PADX 34           // smem row stride for x[k][b]

typedef unsigned long long ull;

// 201 MB scratch for gx[t][g][o][b]
__device__ float g_gx[(size_t)TT * GR * ROWS * BATCH];

__device__ __forceinline__ ull pk(float lo, float hi) {
    ull r;
    asm("mov.b64 %0, {%1, %2};" : "=l"(r) : "f"(lo), "f"(hi));
    return r;
}
__device__ __forceinline__ float2 up(ull v) {
    float2 r;
    asm("mov.b64 {%0, %1}, %2;" : "=f"(r.x), "=f"(r.y) : "l"(v));
    return r;
}
__device__ __forceinline__ void fma2(ull& d, ull a, ull b) {
    asm("fma.rn.f32x2 %0, %1, %2, %0;" : "+l"(d) : "l"(a), "l"(b));
}

__device__ __forceinline__ float sigm(float x) {
    return __fdividef(1.0f, 1.0f + __expf(-x));
}
__device__ __forceinline__ float tanh_(float x) {
    return 1.0f - __fdividef(2.0f, __expf(2.0f * x) + 1.0f);
}

// ============================================================================
// Phase 1: gx[t][g][o][b] = b_ih[g][o] + sum_i W_ih[g][o][i] * x[b][t][g*128+i]
// Grid: 128 CTAs = (tb 0..15) x (g 0..7), 256 threads, W_ih[g] resident in smem.
// ============================================================================
__global__ void __launch_bounds__(256, 1)
gx_kernel(const float* __restrict__ x,
          const float* __restrict__ W_ih,
          const float* __restrict__ b_ih)
{
    extern __shared__ float sm[];
    float* Ws = sm;                   // [128][PADW]   W[k][o]
    float* Xs = sm + 128 * PADW;      // [128][PADX]   x[k][b]

    const int g  = blockIdx.x & 7;
    const int tb = blockIdx.x >> 3;
    const int tid = threadIdx.x;

    // Load W_ih[g] transposed to k-major
    const float* Wg = W_ih + (size_t)g * ROWS * 128;
    for (int idx = tid; idx < ROWS * 128; idx += 256) {
        int o = idx >> 7, k = idx & 127;
        Ws[k * PADW + o] = Wg[idx];
    }

    const int w    = tid >> 5;
    const int lane = tid & 31;
    const int rsub = lane >> 3;       // 0..3
    const int bq   = lane & 7;        // 0..7
    const int ro   = w * 48 + rsub * 12;   // 12 rows per thread
    const int bb   = bq * 4;               // 4 batches per thread

    float bias[12];
#pragma unroll
    for (int i = 0; i < 12; i++) bias[i] = b_ih[g * ROWS + ro + i];

    __syncthreads();

    for (int tt = 0; tt < 32; tt++) {
        const int t = tb * 32 + tt;

        // Load x tile [32 b][128 k] -> Xs[k][b]
#pragma unroll
        for (int r = 0; r < 4; r++) {
            int flat = tid + r * 256;          // 0..1023 float4s
            int b = flat >> 5, kq = flat & 31;
            float4 v = *(const float4*)(x + ((size_t)b * TT + t) * 1024 + g * 128 + kq * 4);
            Xs[(kq * 4 + 0) * PADX + b] = v.x;
            Xs[(kq * 4 + 1) * PADX + b] = v.y;
            Xs[(kq * 4 + 2) * PADX + b] = v.z;
            Xs[(kq * 4 + 3) * PADX + b] = v.w;
        }
        __syncthreads();

        ull acc[6][4];
#pragma unroll
        for (int p = 0; p < 6; p++) {
            ull binit = pk(bias[2 * p], bias[2 * p + 1]);
#pragma unroll
            for (int b = 0; b < 4; b++) acc[p][b] = binit;
        }

#pragma unroll 4
        for (int k = 0; k < 128; k++) {
            const float* wr = Ws + k * PADW + ro;
            float4 w0 = *(const float4*)(wr);
            float4 w1 = *(const float4*)(wr + 4);
            float4 w2 = *(const float4*)(wr + 8);
            ull pw[6];
            pw[0] = pk(w0.x, w0.y); pw[1] = pk(w0.z, w0.w);
            pw[2] = pk(w1.x, w1.y); pw[3] = pk(w1.z, w1.w);
            pw[4] = pk(w2.x, w2.y); pw[5] = pk(w2.z, w2.w);
            float2 xa = *(const float2*)(Xs + k * PADX + bb);
            float2 xb = *(const float2*)(Xs + k * PADX + bb + 2);
            ull xd[4];
            xd[0] = pk(xa.x, xa.x); xd[1] = pk(xa.y, xa.y);
            xd[2] = pk(xb.x, xb.x); xd[3] = pk(xb.y, xb.y);
#pragma unroll
            for (int p = 0; p < 6; p++)
#pragma unroll
                for (int b = 0; b < 4; b++)
                    fma2(acc[p][b], pw[p], xd[b]);
        }

        // Store gx[t][g][o][b]
        float* outp = g_gx + ((size_t)t * GR + g) * ROWS * BATCH;
#pragma unroll
        for (int p = 0; p < 6; p++) {
            float2 u0 = up(acc[p][0]);
            float2 u1 = up(acc[p][1]);
            float2 u2 = up(acc[p][2]);
            float2 u3 = up(acc[p][3]);
            float4 v0 = make_float4(u0.x, u1.x, u2.x, u3.x);
            float4 v1 = make_float4(u0.y, u1.y, u2.y, u3.y);
            *(float4*)(outp + (ro + 2 * p)     * BATCH + bb) = v0;
            *(float4*)(outp + (ro + 2 * p + 1) * BATCH + bb) = v1;
        }
        __syncthreads();
    }
}

// ============================================================================
// Phase 2: recurrence. Grid: 64 CTAs = (g 0..7) x (bq 0..7: 4 batches each),
// 128 threads (thread = hidden unit j). Full W_hh[g] resident in smem.
// ============================================================================
__global__ void __launch_bounds__(128, 1)
gru_kernel(const float* __restrict__ state,
           const float* __restrict__ W_hh,
           const float* __restrict__ b_hh,
           float* __restrict__ out)
{
    extern __shared__ float sm[];
    float* Ws = sm;                    // [128][PADW]  W[k][o]
    float* Hs = sm + 128 * PADW;       // [128][4]     h[k][b_local]

    const int g  = blockIdx.x >> 3;
    const int bq = blockIdx.x & 7;
    const int j  = threadIdx.x;        // 0..127

    // Load W_hh[g] transposed
    const float* Wg = W_hh + (size_t)g * ROWS * 128;
    for (int idx = j; idx < ROWS * 128; idx += 128) {
        int o = idx >> 7, k = idx & 127;
        Ws[k * PADW + o] = Wg[idx];
    }

    // Init h
    {
        float4 h0;
        h0.x = state[((size_t)g * 32 + bq * 4 + 0) * 128 + j];
        h0.y = state[((size_t)g * 32 + bq * 4 + 1) * 128 + j];
        h0.z = state[((size_t)g * 32 + bq * 4 + 2) * 128 + j];
        h0.w = state[((size_t)g * 32 + bq * 4 + 3) * 128 + j];
        *(float4*)(Hs + j * 4) = h0;
    }

    const float bhr = b_hh[g * ROWS + j];
    const float bhz = b_hh[g * ROWS + 128 + j];
    const float bhn = b_hh[g * ROWS + 256 + j];
    const ull br = pk(bhr, bhr), bz = pk(bhz, bhz), bn = pk(bhn, bhn);

    __syncthreads();

    for (int t = 0; t < TT; t++) {
        // gx for this step (r, z, n rows; 4 batches each) — issued early,
        // hidden under the ~1700-cycle K-loop.
        const float* gp = g_gx + ((size_t)t * GR + g) * ROWS * BATCH + j * BATCH + bq * 4;
        float4 gr = *(const float4*)(gp);
        float4 gz = *(const float4*)(gp + 128 * BATCH);
        float4 gn = *(const float4*)(gp + 256 * BATCH);

        ull ar0 = br, ar1 = br, az0 = bz, az1 = bz, an0 = bn, an1 = bn;

#pragma unroll 8
        for (int k = 0; k < 128; k++) {
            ulonglong2 hv = *(const ulonglong2*)(Hs + k * 4);   // (h0,h1),(h2,h3)
            float wr = Ws[k * PADW + j];
            float wz = Ws[k * PADW + 128 + j];
            float wn = Ws[k * PADW + 256 + j];
            ull wr2 = pk(wr, wr), wz2 = pk(wz, wz), wn2 = pk(wn, wn);
            fma2(ar0, wr2, hv.x); fma2(ar1, wr2, hv.y);
            fma2(az0, wz2, hv.x); fma2(az1, wz2, hv.y);
            fma2(an0, wn2, hv.x); fma2(an1, wn2, hv.y);
        }

        float4 hold = *(float4*)(Hs + j * 4);

        float2 rA = up(ar0), rB = up(ar1);
        float2 zA = up(az0), zB = up(az1);
        float2 nA = up(an0), nB = up(an1);
        float rpre[4] = { rA.x, rA.y, rB.x, rB.y };
        float zpre[4] = { zA.x, zA.y, zB.x, zB.y };
        float npre[4] = { nA.x, nA.y, nB.x, nB.y };
        float gxr[4] = { gr.x, gr.y, gr.z, gr.w };
        float gxz[4] = { gz.x, gz.y, gz.z, gz.w };
        float gxn[4] = { gn.x, gn.y, gn.z, gn.w };
        float hov[4] = { hold.x, hold.y, hold.z, hold.w };

        float hn[4];
#pragma unroll
        for (int b = 0; b < 4; b++) {
            float r = sigm(gxr[b] + rpre[b]);
            float z = sigm(gxz[b] + zpre[b]);
            float n = tanh_(gxn[b] + r * npre[b]);
            hn[b] = n + z * (hov[b] - n);
        }

        __syncthreads();   // all reads of Hs for step t done
        *(float4*)(Hs + j * 4) = make_float4(hn[0], hn[1], hn[2], hn[3]);

        // y[b][t][g*128+j]
#pragma unroll
        for (int b = 0; b < 4; b++) {
            out[(((size_t)(bq * 4 + b) * TT) + t) * 1024 + g * 128 + j] = hn[b];
        }
        __syncthreads();   // Hs update visible for step t+1
    }

    // h_out[g][b][j] appended after y
    float4 hf = *(float4*)(Hs + j * 4);
    float* hop = out + (size_t)BATCH * TT * 1024;
    hop[((size_t)g * 32 + bq * 4 + 0) * 128 + j] = hf.x;
    hop[((size_t)g * 32 + bq * 4 + 1) * 128 + j] = hf.y;
    hop[((size_t)g * 32 + bq * 4 + 2) * 128 + j] = hf.z;
    hop[((size_t)g * 32 + bq * 4 + 3) * 128 + j] = hf.w;
}

extern "C" void kernel_launch(void* const* d_in, const int* in_sizes, int n_in,
                              void* d_out, int out_size)
{
    const float* x     = (const float*)d_in[0];
    const float* state = (const float*)d_in[1];
    const float* W_ih  = (const float*)d_in[2];
    const float* W_hh  = (const float*)d_in[3];
    const float* b_ih  = (const float*)d_in[4];
    const float* b_hh  = (const float*)d_in[5];
    float* out = (float*)d_out;

    const int smem1 = (128 * PADW + 128 * PADX) * 4;   // 216,064 B
    const int smem2 = (128 * PADW + 128 * 4) * 4;      // 200,704 B

    cudaFuncSetAttribute(gx_kernel,  cudaFuncAttributeMaxDynamicSharedMemorySize, smem1);
    cudaFuncSetAttribute(gru_kernel, cudaFuncAttributeMaxDynamicSharedMemorySize, smem2);

    gx_kernel<<<128, 256, smem1>>>(x, W_ih, b_ih);
    gru_kernel<<<64, 128, smem2>>>(state, W_hh, b_hh, out);
}

// round 2
// speedup vs baseline: 1.4319x; 1.4319x over previous
#include <cuda_runtime.h>
#include <cuda_bf16.h>
#include <cstdint>

#define GR 8
#define BATCH 32
#define TT 512
#define HGD 128
#define ROWS 384          // 3 * HGD
#define PADW 388          // smem row stride (floats) for W[k][o] (phase 1)
#define PADX 34           // smem row stride for x[k][b] (phase 1)

typedef unsigned long long ull;

// 201 MB scratch for gx[t][g][o][b]
__device__ float g_gx[(size_t)TT * GR * ROWS * BATCH];

__device__ __forceinline__ ull pk(float lo, float hi) {
    ull r;
    asm("mov.b64 %0, {%1, %2};" : "=l"(r) : "f"(lo), "f"(hi));
    return r;
}
__device__ __forceinline__ float2 up(ull v) {
    float2 r;
    asm("mov.b64 {%0, %1}, %2;" : "=f"(r.x), "=f"(r.y) : "l"(v));
    return r;
}
__device__ __forceinline__ void fma2(ull& d, ull a, ull b) {
    asm("fma.rn.f32x2 %0, %1, %2, %0;" : "+l"(d) : "l"(a), "l"(b));
}
__device__ __forceinline__ ull add2(ull a, ull b) {
    ull r;
    asm("add.rn.f32x2 %0, %1, %2;" : "=l"(r) : "l"(a), "l"(b));
    return r;
}

__device__ __forceinline__ float sigm(float x) {
    return __fdividef(1.0f, 1.0f + __expf(-x));
}
__device__ __forceinline__ float tanh_(float x) {
    return 1.0f - __fdividef(2.0f, __expf(2.0f * x) + 1.0f);
}

// ============================================================================
// Phase 1: gx[t][g][o][b] = b_ih[g][o] + sum_i W_ih[g][o][i] * x[b][t][g*128+i]
// Grid: 128 CTAs = (tb 0..15) x (g 0..7), 256 threads, W_ih[g] resident in smem.
// ============================================================================
__global__ void __launch_bounds__(256, 1)
gx_kernel(const float* __restrict__ x,
          const float* __restrict__ W_ih,
          const float* __restrict__ b_ih)
{
    extern __shared__ float sm[];
    float* Ws = sm;                   // [128][PADW]   W[k][o]
    float* Xs = sm + 128 * PADW;      // [128][PADX]   x[k][b]

    const int g  = blockIdx.x & 7;
    const int tb = blockIdx.x >> 3;
    const int tid = threadIdx.x;

    // Load W_ih[g] transposed to k-major
    const float* Wg = W_ih + (size_t)g * ROWS * 128;
    for (int idx = tid; idx < ROWS * 128; idx += 256) {
        int o = idx >> 7, k = idx & 127;
        Ws[k * PADW + o] = Wg[idx];
    }

    const int w    = tid >> 5;
    const int lane = tid & 31;
    const int rsub = lane >> 3;       // 0..3
    const int bq   = lane & 7;        // 0..7
    const int ro   = w * 48 + rsub * 12;   // 12 rows per thread
    const int bb   = bq * 4;               // 4 batches per thread

    float bias[12];
#pragma unroll
    for (int i = 0; i < 12; i++) bias[i] = b_ih[g * ROWS + ro + i];

    __syncthreads();

    for (int tt = 0; tt < 32; tt++) {
        const int t = tb * 32 + tt;

        // Load x tile [32 b][128 k] -> Xs[k][b]
#pragma unroll
        for (int r = 0; r < 4; r++) {
            int flat = tid + r * 256;          // 0..1023 float4s
            int b = flat >> 5, kq = flat & 31;
            float4 v = *(const float4*)(x + ((size_t)b * TT + t) * 1024 + g * 128 + kq * 4);
            Xs[(kq * 4 + 0) * PADX + b] = v.x;
            Xs[(kq * 4 + 1) * PADX + b] = v.y;
            Xs[(kq * 4 + 2) * PADX + b] = v.z;
            Xs[(kq * 4 + 3) * PADX + b] = v.w;
        }
        __syncthreads();

        ull acc[6][4];
#pragma unroll
        for (int p = 0; p < 6; p++) {
            ull binit = pk(bias[2 * p], bias[2 * p + 1]);
#pragma unroll
            for (int b = 0; b < 4; b++) acc[p][b] = binit;
        }

#pragma unroll 4
        for (int k = 0; k < 128; k++) {
            const float* wr = Ws + k * PADW + ro;
            float4 w0 = *(const float4*)(wr);
            float4 w1 = *(const float4*)(wr + 4);
            float4 w2 = *(const float4*)(wr + 8);
            ull pw[6];
            pw[0] = pk(w0.x, w0.y); pw[1] = pk(w0.z, w0.w);
            pw[2] = pk(w1.x, w1.y); pw[3] = pk(w1.z, w1.w);
            pw[4] = pk(w2.x, w2.y); pw[5] = pk(w2.z, w2.w);
            float2 xa = *(const float2*)(Xs + k * PADX + bb);
            float2 xb = *(const float2*)(Xs + k * PADX + bb + 2);
            ull xd[4];
            xd[0] = pk(xa.x, xa.x); xd[1] = pk(xa.y, xa.y);
            xd[2] = pk(xb.x, xb.x); xd[3] = pk(xb.y, xb.y);
#pragma unroll
            for (int p = 0; p < 6; p++)
#pragma unroll
                for (int b = 0; b < 4; b++)
                    fma2(acc[p][b], pw[p], xd[b]);
        }

        // Store gx[t][g][o][b]
        float* outp = g_gx + ((size_t)t * GR + g) * ROWS * BATCH;
#pragma unroll
        for (int p = 0; p < 6; p++) {
            float2 u0 = up(acc[p][0]);
            float2 u1 = up(acc[p][1]);
            float2 u2 = up(acc[p][2]);
            float2 u3 = up(acc[p][3]);
            float4 v0 = make_float4(u0.x, u1.x, u2.x, u3.x);
            float4 v1 = make_float4(u0.y, u1.y, u2.y, u3.y);
            *(float4*)(outp + (ro + 2 * p)     * BATCH + bb) = v0;
            *(float4*)(outp + (ro + 2 * p + 1) * BATCH + bb) = v1;
        }
        __syncthreads();
    }
}

// ============================================================================
// Phase 2: recurrence, register-resident W_hh + k-pair f32x2 packing.
// Grid: 128 CTAs = (g 0..7) x (bp 0..15: batches 2bp, 2bp+1).
// 512 threads = (q 0..3: k-chunk of 32) x (j 0..127: output unit).
// Each thread holds W_hh rows {j, 128+j, 256+j}, cols [q*32, q*32+32) in
// registers, pre-packed as f32x2 over adjacent k. K-loop has NO weight loads
// and NO packing instructions: 2 broadcast LDS.64 + 6 fma2 per k-pair.
// Cross-q reduction through smem, 128 reducer threads do the gate math.
// ============================================================================
__global__ void __launch_bounds__(512, 1)
gru_kernel(const float* __restrict__ state,
           const float* __restrict__ W_hh,
           const float* __restrict__ b_hh,
           float* __restrict__ out)
{
    // partials: slot s = gate*2 + batch (0..5), layout [s][q][j]
    __shared__ ull part[6 * 4 * 128];           // 24 KB
    __shared__ __align__(16) float Hb0[128];    // h for batch 0 of the pair
    __shared__ __align__(16) float Hb1[128];

    const int g   = blockIdx.x >> 4;
    const int bp  = blockIdx.x & 15;
    const int tid = threadIdx.x;
    const int q   = tid >> 7;       // 0..3
    const int j   = tid & 127;      // 0..127
    const int b0  = bp * 2;
    const int b1  = b0 + 1;

    // ---- load W_hh rows (j, 128+j, 256+j), cols q*32..q*32+31, as k-pairs ----
    ull wr[16], wz[16], wn[16];
    {
        const float* base = W_hh + (size_t)g * ROWS * 128 + q * 32;
        const float* pr = base + (size_t)(j)       * 128;
        const float* pz = base + (size_t)(128 + j) * 128;
        const float* pn = base + (size_t)(256 + j) * 128;
#pragma unroll
        for (int i = 0; i < 8; i++) {
            ulonglong2 a = *(const ulonglong2*)(pr + i * 4);
            wr[2 * i] = a.x; wr[2 * i + 1] = a.y;
            ulonglong2 b = *(const ulonglong2*)(pz + i * 4);
            wz[2 * i] = b.x; wz[2 * i + 1] = b.y;
            ulonglong2 c = *(const ulonglong2*)(pn + i * 4);
            wn[2 * i] = c.x; wn[2 * i + 1] = c.y;
        }
    }

    // biases (used by reducer threads only)
    const float bhr = b_hh[g * ROWS + j];
    const float bhz = b_hh[g * ROWS + 128 + j];
    const float bhn = b_hh[g * ROWS + 256 + j];

    // init h
    if (tid < 128) {
        Hb0[j] = state[((size_t)g * 32 + b0) * 128 + j];
        Hb1[j] = state[((size_t)g * 32 + b1) * 128 + j];
    }
    __syncthreads();

    const float* gx_base = g_gx + (size_t)g * ROWS * BATCH;

    for (int t = 0; t < TT; t++) {
        // prefetch gx for this step (reducer threads), hidden under the K-loop
        float2 gxr, gxz, gxn;
        if (q == 0) {
            const float* gp = gx_base + (size_t)t * (GR * ROWS * BATCH) + b0;
            gxr = *(const float2*)(gp + (size_t)(j)       * BATCH);
            gxz = *(const float2*)(gp + (size_t)(128 + j) * BATCH);
            gxn = *(const float2*)(gp + (size_t)(256 + j) * BATCH);
        }

        ull ar0 = 0, az0 = 0, an0 = 0;   // batch b0, packed (even-k, odd-k)
        ull ar1 = 0, az1 = 0, an1 = 0;   // batch b1

#pragma unroll
        for (int i = 0; i < 16; i++) {
            const int k = q * 32 + i * 2;
            ull h0 = *(const ull*)(&Hb0[k]);   // broadcast within warp
            ull h1 = *(const ull*)(&Hb1[k]);
            fma2(ar0, wr[i], h0);
            fma2(az0, wz[i], h0);
            fma2(an0, wn[i], h0);
            fma2(ar1, wr[i], h1);
            fma2(az1, wz[i], h1);
            fma2(an1, wn[i], h1);
        }

        part[(0 * 4 + q) * 128 + j] = ar0;
        part[(1 * 4 + q) * 128 + j] = ar1;
        part[(2 * 4 + q) * 128 + j] = az0;
        part[(3 * 4 + q) * 128 + j] = az1;
        part[(4 * 4 + q) * 128 + j] = an0;
        part[(5 * 4 + q) * 128 + j] = an1;
        __syncthreads();

        if (q == 0) {
            // reduce 4 q-partials per slot, then the two packed halves
            float pre[6];
#pragma unroll
            for (int s = 0; s < 6; s++) {
                const ull* p = part + s * 512 + j;
                ull v = add2(add2(p[0], p[128]), add2(p[256], p[384]));
                float2 u = up(v);
                pre[s] = u.x + u.y;
            }
            float hold0 = Hb0[j], hold1 = Hb1[j];

            float r0 = sigm(gxr.x + pre[0] + bhr);
            float r1 = sigm(gxr.y + pre[1] + bhr);
            float z0 = sigm(gxz.x + pre[2] + bhz);
            float z1 = sigm(gxz.y + pre[3] + bhz);
            float n0 = tanh_(gxn.x + r0 * (pre[4] + bhn));
            float n1 = tanh_(gxn.y + r1 * (pre[5] + bhn));
            float h0n = n0 + z0 * (hold0 - n0);
            float h1n = n1 + z1 * (hold1 - n1);

            Hb0[j] = h0n;
            Hb1[j] = h1n;

            out[((size_t)b0 * TT + t) * 1024 + g * 128 + j] = h0n;
            out[((size_t)b1 * TT + t) * 1024 + g * 128 + j] = h1n;
        }
        __syncthreads();
    }

    // h_out[g][b][j] appended after y
    if (tid < 128) {
        float* hop = out + (size_t)BATCH * TT * 1024;
        hop[((size_t)g * 32 + b0) * 128 + j] = Hb0[j];
        hop[((size_t)g * 32 + b1) * 128 + j] = Hb1[j];
    }
}

extern "C" void kernel_launch(void* const* d_in, const int* in_sizes, int n_in,
                              void* d_out, int out_size)
{
    const float* x     = (const float*)d_in[0];
    const float* state = (const float*)d_in[1];
    const float* W_ih  = (const float*)d_in[2];
    const float* W_hh  = (const float*)d_in[3];
    const float* b_ih  = (const float*)d_in[4];
    const float* b_hh  = (const float*)d_in[5];
    float* out = (float*)d_out;

    const int smem1 = (128 * PADW + 128 * PADX) * 4;   // 216,064 B

    cudaFuncSetAttribute(gx_kernel, cudaFuncAttributeMaxDynamicSharedMemorySize, smem1);

    gx_kernel<<<128, 256, smem1>>>(x, W_ih, b_ih);
    gru_kernel<<<128, 512>>>(state, W_hh, b_hh, out);
}